// round 3
// baseline (speedup 1.0000x reference)
#include <cuda_runtime.h>
#include <cstdint>

// Problem constants (fixed by the dataset)
#define KMAX 24   // max n-grams per word
#define EV4  32   // E=128 floats = 32 float4 per row

// word_idx:      [B*S]      int32
// ngram_ids:     [V, 24]    int32   (slot >= count padded with 0; id 0 == zero row)
// ngram_counts:  [V]        int32
// emb_table:     [NG, 128]  float32
// out:           [B*S, 128] float32  = mean over valid ngram embeddings
//
// One warp per word (grid-stride persistent loop); lane l owns float4 #l of
// the 128-float row. Output is written with st.global.wt so it never
// allocates dirty lines in L2 -> the 102MB table stays L2-resident across
// graph replays (L2 = 126MB).
__global__ __launch_bounds__(256, 6)
void ngram_emb_kernel(const int* __restrict__ word_idx,
                      const int* __restrict__ ngram_ids,
                      const int* __restrict__ ngram_counts,
                      const float4* __restrict__ emb,   // [NG, 32] float4
                      float4* __restrict__ out,         // [B*S, 32] float4
                      int n_words) {
    const int lane = threadIdx.x & 31;
    const int warp0 = (blockIdx.x * blockDim.x + threadIdx.x) >> 5;
    const int nwarps = (gridDim.x * blockDim.x) >> 5;

    for (int word = warp0; word < n_words; word += nwarps) {
        const int w = __ldg(&word_idx[word]);

        // Lanes 0..23 fetch the 24 ngram ids for this word (coalesced 96B).
        int id_l = 0;
        if (lane < KMAX) id_l = __ldg(&ngram_ids[w * KMAX + lane]);
        const int cnt = __ldg(&ngram_counts[w]);

        float4 a0 = make_float4(0.f, 0.f, 0.f, 0.f);
        float4 a1 = make_float4(0.f, 0.f, 0.f, 0.f);
        float4 a2 = make_float4(0.f, 0.f, 0.f, 0.f);
        float4 a3 = make_float4(0.f, 0.f, 0.f, 0.f);

        #pragma unroll
        for (int k = 0; k < KMAX; k += 4) {
            const int i0 = __shfl_sync(0xffffffffu, id_l, k + 0);
            const int i1 = __shfl_sync(0xffffffffu, id_l, k + 1);
            const int i2 = __shfl_sync(0xffffffffu, id_l, k + 2);
            const int i3 = __shfl_sync(0xffffffffu, id_l, k + 3);
            // id 0 is the padding row -> contributes zero; skip the load.
            if (i0) { float4 v = __ldg(&emb[(size_t)i0 * EV4 + lane]);
                      a0.x += v.x; a0.y += v.y; a0.z += v.z; a0.w += v.w; }
            if (i1) { float4 v = __ldg(&emb[(size_t)i1 * EV4 + lane]);
                      a1.x += v.x; a1.y += v.y; a1.z += v.z; a1.w += v.w; }
            if (i2) { float4 v = __ldg(&emb[(size_t)i2 * EV4 + lane]);
                      a2.x += v.x; a2.y += v.y; a2.z += v.z; a2.w += v.w; }
            if (i3) { float4 v = __ldg(&emb[(size_t)i3 * EV4 + lane]);
                      a3.x += v.x; a3.y += v.y; a3.z += v.z; a3.w += v.w; }
        }

        const float inv = 1.0f / (float)cnt;
        float4 r;
        r.x = (a0.x + a1.x + a2.x + a3.x) * inv;
        r.y = (a0.y + a1.y + a2.y + a3.y) * inv;
        r.z = (a0.z + a1.z + a2.z + a3.z) * inv;
        r.w = (a0.w + a1.w + a2.w + a3.w) * inv;
        // Write-through: do not pollute L2 with output lines.
        __stwt(&out[(size_t)word * EV4 + lane], r);
    }
}

extern "C" void kernel_launch(void* const* d_in, const int* in_sizes, int n_in,
                              void* d_out, int out_size) {
    const int*   word_idx     = (const int*)d_in[0];   // [B*S]
    const int*   ngram_ids    = (const int*)d_in[1];   // [V*24]
    const int*   ngram_counts = (const int*)d_in[2];   // [V]
    const float* emb_table    = (const float*)d_in[3]; // [NG*128]
    float*       out          = (float*)d_out;

    const int n_words = in_sizes[0];                   // 32768
    const int threads = 256;                           // 8 warps / block
    const int blocks  = 1184;                          // 148 SMs * 8 blocks

    ngram_emb_kernel<<<blocks, threads>>>(word_idx, ngram_ids, ngram_counts,
                                          (const float4*)emb_table,
                                          (float4*)out, n_words);
}

// round 5
// speedup vs baseline: 1.2680x; 1.2680x over previous
#include <cuda_runtime.h>
#include <cstdint>

// Problem constants (fixed by the dataset)
#define KMAX      24    // max n-grams per word
#define ROW_BYTES 512   // E=128 fp32

// Dummy zero row for padding id 0 (reference zeroes table row 0; the raw
// input table row 0 is NOT zero, so we redirect id==0 here). Static device
// global = allowed scratch; .bss so it is zero-initialized.
__device__ __align__(256) float g_zero_row[128];

// 256-bit table gather, L2 evict_last (keep the 102MB table resident in the
// 126MB L2 across graph replays; output stream is evict_first below).
__device__ __forceinline__ void ldg256_evl(const void* p, uint64_t d[4]) {
    asm("ld.global.nc.L2::evict_last.v4.b64 {%0,%1,%2,%3}, [%4];"
        : "=l"(d[0]), "=l"(d[1]), "=l"(d[2]), "=l"(d[3])
        : "l"(p));
}

// 256-bit output store, L2 evict_first (pure 16.8MB stream, never re-read).
__device__ __forceinline__ void stg256_evf(void* p, uint64_t q0, uint64_t q1,
                                           uint64_t q2, uint64_t q3) {
    asm volatile("st.global.L2::evict_first.v4.b64 [%0], {%1,%2,%3,%4};"
                 :: "l"(p), "l"(q0), "l"(q1), "l"(q2), "l"(q3)
                 : "memory");
}

// word_idx:      [B*S]      int32
// ngram_ids:     [V, 24]    int32   (slot >= count padded with 0)
// ngram_counts:  [V]        int32
// emb_table:     [NG, 128]  float32
// out:           [B*S, 128] float32 = mean over valid ngram embeddings
//
// One warp per word. Each LDG.256 fetches TWO ngram rows: lanes 0-15 cover
// the even slot (32B each), lanes 16-31 the odd slot. 12 load instructions
// per word instead of 24. Halves combined with shfl_xor(16) at the end.
__global__ __launch_bounds__(256, 6)
void ngram_emb_kernel(const int* __restrict__ word_idx,
                      const int* __restrict__ ngram_ids,
                      const int* __restrict__ ngram_counts,
                      const char* __restrict__ emb,    // byte view of table
                      char* __restrict__ out,          // byte view of output
                      int n_words) {
    const int warp = (blockIdx.x * blockDim.x + threadIdx.x) >> 5;
    const int lane = threadIdx.x & 31;
    if (warp >= n_words) return;

    const int half = lane >> 4;       // 0: even slots, 1: odd slots
    const int sub  = lane & 15;       // 32B chunk within the 512B row

    const int w = __ldg(&word_idx[warp]);

    // Lanes 0..23 fetch the 24 ngram ids for this word (coalesced 96B read).
    int id_l = 0;
    if (lane < KMAX) id_l = __ldg(&ngram_ids[w * KMAX + lane]);
    const int cnt = __ldg(&ngram_counts[w]);

    const char* zrow = (const char*)g_zero_row + sub * 32;

    float acc[8];
    #pragma unroll
    for (int i = 0; i < 8; ++i) acc[i] = 0.f;

    #pragma unroll
    for (int t = 0; t < KMAX / 2; ++t) {
        const int id = __shfl_sync(0xffffffffu, id_l, 2 * t + half);
        // Branchless: padding id 0 reads the zero row (hot in L1/L2).
        const void* p = id ? (const void*)(emb + (size_t)id * ROW_BYTES + sub * 32)
                           : (const void*)zrow;
        uint64_t d[4];
        ldg256_evl(p, d);
        #pragma unroll
        for (int i = 0; i < 4; ++i) {
            acc[2 * i + 0] += __uint_as_float((uint32_t)d[i]);
            acc[2 * i + 1] += __uint_as_float((uint32_t)(d[i] >> 32));
        }
    }

    // Combine even-slot half and odd-slot half.
    #pragma unroll
    for (int i = 0; i < 8; ++i)
        acc[i] += __shfl_xor_sync(0xffffffffu, acc[i], 16);

    const float inv = 1.0f / (float)cnt;
    if (half == 0) {
        uint64_t q[4];
        #pragma unroll
        for (int i = 0; i < 4; ++i) {
            const uint32_t lo = __float_as_uint(acc[2 * i + 0] * inv);
            const uint32_t hi = __float_as_uint(acc[2 * i + 1] * inv);
            q[i] = (uint64_t)lo | ((uint64_t)hi << 32);
        }
        stg256_evf(out + (size_t)warp * ROW_BYTES + sub * 32,
                   q[0], q[1], q[2], q[3]);
    }
}

extern "C" void kernel_launch(void* const* d_in, const int* in_sizes, int n_in,
                              void* d_out, int out_size) {
    const int*   word_idx     = (const int*)d_in[0];   // [B*S]
    const int*   ngram_ids    = (const int*)d_in[1];   // [V*24]
    const int*   ngram_counts = (const int*)d_in[2];   // [V]
    const char*  emb_table    = (const char*)d_in[3];  // [NG*128] f32
    char*        outp         = (char*)d_out;

    const int n_words = in_sizes[0];                   // 32768
    const int threads = 256;                           // 8 warps / block
    const int warps_per_block = threads / 32;
    const int blocks = (n_words + warps_per_block - 1) / warps_per_block;

    ngram_emb_kernel<<<blocks, threads>>>(word_idx, ngram_ids, ngram_counts,
                                          emb_table, outp, n_words);
}

// round 6
// speedup vs baseline: 1.3036x; 1.0281x over previous
#include <cuda_runtime.h>
#include <cstdint>

// Problem constants (fixed by the dataset)
#define KMAX      24    // max n-grams per word
#define ROW_BYTES 512   // E=128 fp32

// Zero row for the odd trailing slot when cnt is odd (padded id 0 -> zero
// contribution; raw table row 0 is NOT zero, reference zeroes it).
// Static device global = allowed scratch; .bss so it is zero-initialized.
__device__ __align__(256) float g_zero_row[128];

// 256-bit table gather, L2 evict_last (keep the 102MB table resident in the
// 126MB L2 across graph replays; output stream is evict_first below).
__device__ __forceinline__ void ldg256_evl(const void* p, uint64_t d[4]) {
    asm("ld.global.nc.L2::evict_last.v4.b64 {%0,%1,%2,%3}, [%4];"
        : "=l"(d[0]), "=l"(d[1]), "=l"(d[2]), "=l"(d[3])
        : "l"(p));
}

// 256-bit output store, L2 evict_first (pure 16.8MB stream, never re-read).
__device__ __forceinline__ void stg256_evf(void* p, uint64_t q0, uint64_t q1,
                                           uint64_t q2, uint64_t q3) {
    asm volatile("st.global.L2::evict_first.v4.b64 [%0], {%1,%2,%3,%4};"
                 :: "l"(p), "l"(q0), "l"(q1), "l"(q2), "l"(q3)
                 : "memory");
}

// word_idx:      [B*S]      int32
// ngram_ids:     [V, 24]    int32   (slot >= count padded with 0)
// ngram_counts:  [V]        int32
// emb_table:     [NG, 128]  float32
// out:           [B*S, 128] float32 = mean over valid ngram embeddings
//
// One warp per word. Each LDG.256 fetches TWO ngram rows: lanes 0-15 cover
// the even slot (32B each), lanes 16-31 the odd slot. cnt is warp-uniform,
// so we process only ceil(cnt/2) pairs (avg ~6.9 instead of 12) with a
// divergence-free break. Halves combined with shfl_xor(16) at the end.
__global__ __launch_bounds__(256, 6)
void ngram_emb_kernel(const int* __restrict__ word_idx,
                      const int* __restrict__ ngram_ids,
                      const int* __restrict__ ngram_counts,
                      const char* __restrict__ emb,    // byte view of table
                      char* __restrict__ out,          // byte view of output
                      int n_words) {
    const int warp = (blockIdx.x * blockDim.x + threadIdx.x) >> 5;
    const int lane = threadIdx.x & 31;
    if (warp >= n_words) return;

    const int half = lane >> 4;       // 0: even slots, 1: odd slots
    const int sub  = lane & 15;       // 32B chunk within the 512B row

    const int w = __ldg(&word_idx[warp]);

    // Lanes 0..23 fetch the 24 ngram ids for this word (coalesced 96B read).
    int id_l = 0;
    if (lane < KMAX) id_l = __ldg(&ngram_ids[w * KMAX + lane]);
    const int cnt = __ldg(&ngram_counts[w]);
    const int pairs = (cnt + 1) >> 1;   // warp-uniform trip count

    const char* zrow = (const char*)g_zero_row + sub * 32;

    float acc[8];
    #pragma unroll
    for (int i = 0; i < 8; ++i) acc[i] = 0.f;

    #pragma unroll
    for (int t = 0; t < KMAX / 2; ++t) {
        if (t >= pairs) break;          // warp-uniform: no divergence
        const int id = __shfl_sync(0xffffffffu, id_l, 2 * t + half);
        // Only the odd trailing slot (cnt odd) has id==0 here -> zero row.
        const void* p = id ? (const void*)(emb + (size_t)id * ROW_BYTES + sub * 32)
                           : (const void*)zrow;
        uint64_t d[4];
        ldg256_evl(p, d);
        #pragma unroll
        for (int i = 0; i < 4; ++i) {
            acc[2 * i + 0] += __uint_as_float((uint32_t)d[i]);
            acc[2 * i + 1] += __uint_as_float((uint32_t)(d[i] >> 32));
        }
    }

    // Combine even-slot half and odd-slot half.
    #pragma unroll
    for (int i = 0; i < 8; ++i)
        acc[i] += __shfl_xor_sync(0xffffffffu, acc[i], 16);

    const float inv = 1.0f / (float)cnt;
    if (half == 0) {
        uint64_t q[4];
        #pragma unroll
        for (int i = 0; i < 4; ++i) {
            const uint32_t lo = __float_as_uint(acc[2 * i + 0] * inv);
            const uint32_t hi = __float_as_uint(acc[2 * i + 1] * inv);
            q[i] = (uint64_t)lo | ((uint64_t)hi << 32);
        }
        stg256_evf(out + (size_t)warp * ROW_BYTES + sub * 32,
                   q[0], q[1], q[2], q[3]);
    }
}

extern "C" void kernel_launch(void* const* d_in, const int* in_sizes, int n_in,
                              void* d_out, int out_size) {
    const int*   word_idx     = (const int*)d_in[0];   // [B*S]
    const int*   ngram_ids    = (const int*)d_in[1];   // [V*24]
    const int*   ngram_counts = (const int*)d_in[2];   // [V]
    const char*  emb_table    = (const char*)d_in[3];  // [NG*128] f32
    char*        outp         = (char*)d_out;

    const int n_words = in_sizes[0];                   // 32768
    const int threads = 256;                           // 8 warps / block
    const int warps_per_block = threads / 32;
    const int blocks = (n_words + warps_per_block - 1) / warps_per_block;

    ngram_emb_kernel<<<blocks, threads>>>(word_idx, ngram_ids, ngram_counts,
                                          emb_table, outp, n_words);
}